// round 6
// baseline (speedup 1.0000x reference)
#include <cuda_runtime.h>

#define H 480
#define W 640
#define P 256
#define GROUPS_PER_ROW (W / 4)          // 160
#define GROUPS_PER_PAIR (H * GROUPS_PER_ROW)  // 76800

// Scratch for box average (allocation-free per harness rules)
__device__ __align__(16) float g_tmp[H * W];
__device__ __align__(16) float g_box[H * W];

// ---------------------------------------------------------------------------
// Pass 1: horizontal 5-tap sum with edge clamp
// ---------------------------------------------------------------------------
__global__ void hbox_kernel(const float* __restrict__ x) {
    int idx = blockIdx.x * blockDim.x + threadIdx.x;
    if (idx >= H * W) return;
    int y = idx / W;
    int xx = idx - y * W;
    const float* row = x + y * W;
    float s = 0.0f;
#pragma unroll
    for (int d = -2; d <= 2; d++) {
        int xc = xx + d;
        xc = xc < 0 ? 0 : (xc > W - 1 ? W - 1 : xc);
        s += row[xc];
    }
    g_tmp[idx] = s;
}

// ---------------------------------------------------------------------------
// Pass 2: vertical 5-tap sum with edge clamp, divide by 25
// ---------------------------------------------------------------------------
__global__ void vbox_kernel() {
    int idx = blockIdx.x * blockDim.x + threadIdx.x;
    if (idx >= H * W) return;
    int y = idx / W;
    int xx = idx - y * W;
    float s = 0.0f;
#pragma unroll
    for (int d = -2; d <= 2; d++) {
        int yc = y + d;
        yc = yc < 0 ? 0 : (yc > H - 1 ? H - 1 : yc);
        s += g_tmp[yc * W + xx];
    }
    g_box[idx] = s / 25.0f;
}

// ---------------------------------------------------------------------------
// One bilinear translational sample for 4 consecutive x-pixels.
// Pure-translation grid => integer shift + constant fraction per (pair,sample).
// Fast path: 2 aligned float4 loads per row (window [c, c+4] always inside
// [c-r, c-r+8) since r = c&3 <= 3). Border groups use scalar clamped path.
// ---------------------------------------------------------------------------
__device__ __forceinline__ float4 sample_one(int y, int gx, float dy, float dx) {
    // vertical: per-row constants
    float py = fminf(fmaxf((float)y + dy, 0.0f), (float)(H - 1));
    float yAf = floorf(py);
    int   yA  = (int)yAf;
    float fy  = py - yAf;
    int   yB  = min(yA + 1, H - 1);
    const float* rA = g_box + yA * W;
    const float* rB = g_box + yB * W;

    float ixf = floorf(dx);
    int   ix  = (int)ixf;
    float fx  = dx - ixf;
    int   c   = gx + ix;

    float4 o;
    if (c >= 3 && c <= W - 8) {   // base >= 0 and base+8 <= W, window fully interior
        int base = c & ~3;
        int r    = c & 3;         // uniform across the block (gx % 4 == 0)
        float4 a0 = *reinterpret_cast<const float4*>(rA + base);
        float4 a1 = *reinterpret_cast<const float4*>(rA + base + 4);
        float4 b0 = *reinterpret_cast<const float4*>(rB + base);
        float4 b1 = *reinterpret_cast<const float4*>(rB + base + 4);
        // vertical lerp over the 8-float window
        float v0 = fmaf(fy, b0.x - a0.x, a0.x);
        float v1 = fmaf(fy, b0.y - a0.y, a0.y);
        float v2 = fmaf(fy, b0.z - a0.z, a0.z);
        float v3 = fmaf(fy, b0.w - a0.w, a0.w);
        float v4 = fmaf(fy, b1.x - a1.x, a1.x);
        float v5 = fmaf(fy, b1.y - a1.y, a1.y);
        float v6 = fmaf(fy, b1.z - a1.z, a1.z);
        float v7 = fmaf(fy, b1.w - a1.w, a1.w);
        float w0, w1, w2, w3, w4;
        switch (r) {
            case 0: w0 = v0; w1 = v1; w2 = v2; w3 = v3; w4 = v4; break;
            case 1: w0 = v1; w1 = v2; w2 = v3; w3 = v4; w4 = v5; break;
            case 2: w0 = v2; w1 = v3; w2 = v4; w3 = v5; w4 = v6; break;
            default: w0 = v3; w1 = v4; w2 = v5; w3 = v6; w4 = v7; break;
        }
        o.x = fmaf(fx, w1 - w0, w0);
        o.y = fmaf(fx, w2 - w1, w1);
        o.z = fmaf(fx, w3 - w2, w2);
        o.w = fmaf(fx, w4 - w3, w3);
    } else {
        // scalar border path with full clamping
        float res[4];
#pragma unroll
        for (int k = 0; k < 4; k++) {
            float pxc = fminf(fmaxf((float)(gx + k) + dx, 0.0f), (float)(W - 1));
            float x0f = floorf(pxc);
            int   x0  = (int)x0f;
            int   x1  = min(x0 + 1, W - 1);
            float wx  = pxc - x0f;
            float vA  = fmaf(wx, rA[x1] - rA[x0], rA[x0]);
            float vB  = fmaf(wx, rB[x1] - rB[x0], rB[x0]);
            res[k]    = fmaf(fy, vB - vA, vA);
        }
        o.x = res[0]; o.y = res[1]; o.z = res[2]; o.w = res[3];
    }
    return o;
}

// ---------------------------------------------------------------------------
// Main kernel: one thread -> one float4 (4 x-pixels) of one (pair,row).
// ---------------------------------------------------------------------------
__global__ void __launch_bounds__(256) descriptor_kernel(
    const float* __restrict__ offs, float* __restrict__ out)
{
    int p = blockIdx.y;
    int g = blockIdx.x * blockDim.x + threadIdx.x;   // 0 .. GROUPS_PER_PAIR-1
    int y  = g / GROUPS_PER_ROW;
    int gx = (g - y * GROUPS_PER_ROW) * 4;

    const float* po = offs + p * 4;
    float dy1 = po[0], dx1 = po[1];
    float dy2 = po[2], dx2 = po[3];

    float4 s1 = sample_one(y, gx, dy1, dx1);
    float4 s2 = sample_one(y, gx, dy2, dx2);

    float4 r;
    r.x = s1.x - s2.x;
    r.y = s1.y - s2.y;
    r.z = s1.z - s2.z;
    r.w = s1.w - s2.w;

    *reinterpret_cast<float4*>(out + ((size_t)p * H + y) * W + gx) = r;
}

extern "C" void kernel_launch(void* const* d_in, const int* in_sizes, int n_in,
                              void* d_out, int out_size) {
    const float* x    = (const float*)d_in[0];   // [1,1,480,640]
    const float* offs = (const float*)d_in[1];   // [256,2,2]
    float* out = (float*)d_out;                  // [1,256,480,640]

    const int npx = H * W;
    hbox_kernel<<<(npx + 255) / 256, 256>>>(x);
    vbox_kernel<<<(npx + 255) / 256, 256>>>();

    dim3 grid(GROUPS_PER_PAIR / 256, P, 1);      // 300 x 256 blocks
    descriptor_kernel<<<grid, 256>>>(offs, out);
}

// round 7
// speedup vs baseline: 1.1167x; 1.1167x over previous
#include <cuda_runtime.h>

#define H 480
#define W 640
#define P 256
#define ROWS 4
#define GROUPS_PER_ROW (W / 4)   // 160

// Scratch for box average (allocation-free per harness rules)
__device__ __align__(16) float g_tmp[H * W];
__device__ __align__(16) float g_box[H * W];

// ---------------------------------------------------------------------------
// Pass 1: horizontal 5-tap sum, edge clamp. 4 px / thread, float4 loads.
// ---------------------------------------------------------------------------
__global__ void hbox_kernel(const float* __restrict__ x) {
    int idx = blockIdx.x * blockDim.x + threadIdx.x;   // group index
    if (idx >= H * GROUPS_PER_ROW) return;
    int y = idx / GROUPS_PER_ROW;
    int t = idx - y * GROUPS_PER_ROW;
    const float* row = x + y * W;
    float4 o;
    if (t >= 1 && t <= GROUPS_PER_ROW - 2) {
        float4 m1 = *(const float4*)(row + 4 * t - 4);
        float4 c0 = *(const float4*)(row + 4 * t);
        float4 p1 = *(const float4*)(row + 4 * t + 4);
        float s = c0.x + c0.y + c0.z;
        o.x = s + m1.z + m1.w;
        o.y = s + m1.w + c0.w;
        o.z = s + c0.w + p1.x;
        o.w = c0.y + c0.z + c0.w + p1.x + p1.y;
    } else {
        float r[4];
#pragma unroll
        for (int k = 0; k < 4; k++) {
            int xx = 4 * t + k;
            float s = 0.0f;
#pragma unroll
            for (int d = -2; d <= 2; d++) {
                int xc = min(max(xx + d, 0), W - 1);
                s += row[xc];
            }
            r[k] = s;
        }
        o = make_float4(r[0], r[1], r[2], r[3]);
    }
    *(float4*)(g_tmp + y * W + 4 * t) = o;
}

// ---------------------------------------------------------------------------
// Pass 2: vertical 5-tap sum, edge clamp, /25. 4 px / thread.
// ---------------------------------------------------------------------------
__global__ void vbox_kernel() {
    int idx = blockIdx.x * blockDim.x + threadIdx.x;
    if (idx >= H * GROUPS_PER_ROW) return;
    int y = idx / GROUPS_PER_ROW;
    int t = idx - y * GROUPS_PER_ROW;
    float4 s = make_float4(0.f, 0.f, 0.f, 0.f);
#pragma unroll
    for (int d = -2; d <= 2; d++) {
        int yc = min(max(y + d, 0), H - 1);
        float4 v = *(const float4*)(g_tmp + yc * W + 4 * t);
        s.x += v.x; s.y += v.y; s.z += v.z; s.w += v.w;
    }
    const float inv = 1.0f / 25.0f;
    s.x *= inv; s.y *= inv; s.z *= inv; s.w *= inv;
    *(float4*)(g_box + y * W + 4 * t) = s;
}

// ---------------------------------------------------------------------------
// General single-row bilinear sample for 4 consecutive x-pixels (full clamps).
// Used only on y-border blocks and x-border lanes.
// ---------------------------------------------------------------------------
__device__ __forceinline__ float4 sample_row_general(int y, int gx, float dy, float dx) {
    float py  = fminf(fmaxf((float)y + dy, 0.0f), (float)(H - 1));
    float yAf = floorf(py);
    int   yA  = (int)yAf;
    float fy  = py - yAf;
    int   yB  = min(yA + 1, H - 1);
    const float* rA = g_box + yA * W;
    const float* rB = g_box + yB * W;

    float ixf = floorf(dx);
    int   ix  = (int)ixf;
    float fx  = dx - ixf;
    int   c   = gx + ix;

    float4 o;
    if (c >= 0 && c <= W - 5) {
        int base = c & ~3;
        int r    = c & 3;
        float4 a0 = __ldg((const float4*)(rA + base));
        float4 a1 = __ldg((const float4*)(rA + base + 4));
        float4 b0 = __ldg((const float4*)(rB + base));
        float4 b1 = __ldg((const float4*)(rB + base + 4));
        float v0 = fmaf(fy, b0.x - a0.x, a0.x);
        float v1 = fmaf(fy, b0.y - a0.y, a0.y);
        float v2 = fmaf(fy, b0.z - a0.z, a0.z);
        float v3 = fmaf(fy, b0.w - a0.w, a0.w);
        float v4 = fmaf(fy, b1.x - a1.x, a1.x);
        float v5 = fmaf(fy, b1.y - a1.y, a1.y);
        float v6 = fmaf(fy, b1.z - a1.z, a1.z);
        float v7 = fmaf(fy, b1.w - a1.w, a1.w);
        float w0, w1, w2, w3, w4;
        switch (r) {
            case 0:  w0 = v0; w1 = v1; w2 = v2; w3 = v3; w4 = v4; break;
            case 1:  w0 = v1; w1 = v2; w2 = v3; w3 = v4; w4 = v5; break;
            case 2:  w0 = v2; w1 = v3; w2 = v4; w3 = v5; w4 = v6; break;
            default: w0 = v3; w1 = v4; w2 = v5; w3 = v6; w4 = v7; break;
        }
        o.x = fmaf(fx, w1 - w0, w0);
        o.y = fmaf(fx, w2 - w1, w1);
        o.z = fmaf(fx, w3 - w2, w2);
        o.w = fmaf(fx, w4 - w3, w3);
    } else {
        float res[4];
#pragma unroll
        for (int k = 0; k < 4; k++) {
            float pxc = fminf(fmaxf((float)(gx + k) + dx, 0.0f), (float)(W - 1));
            float x0f = floorf(pxc);
            int   x0  = (int)x0f;
            int   x1  = min(x0 + 1, W - 1);
            float wx  = pxc - x0f;
            float vA  = fmaf(wx, rA[x1] - rA[x0], rA[x0]);
            float vB  = fmaf(wx, rB[x1] - rB[x0], rB[x0]);
            res[k]    = fmaf(fy, vB - vA, vA);
        }
        o = make_float4(res[0], res[1], res[2], res[3]);
    }
    return o;
}

// ---------------------------------------------------------------------------
// One sample, 4 consecutive output rows per thread. Fast path streams 5 row-
// pairs of float4s (row B of y is row A of y+1 -> each row loaded once).
// SUB=false: acc = s; SUB=true: acc -= s.
// ---------------------------------------------------------------------------
template <bool SUB>
__device__ __forceinline__ void do_sample(int y0, int gx, float dy, float dx, float4* acc) {
    float ixf = floorf(dx);
    int   ix  = (int)ixf;
    float fx  = dx - ixf;
    int   c   = gx + ix;
    float py0 = (float)y0 + dy;

    bool fast = (py0 >= 0.0f) && (py0 + (float)(ROWS - 1) < (float)(H - 1))
             && (c >= 0) && (c <= W - 5);

    if (fast) {
        float Y0f = floorf(py0);
        int   Y0  = (int)Y0f;
        float fy  = py0 - Y0f;
        int   base = c & ~3;
        int   r    = c & 3;
        const float* rp = g_box + Y0 * W + base;
        float4 A = __ldg((const float4*)rp);
        float4 B = __ldg((const float4*)(rp + 4));
#pragma unroll
        for (int i = 0; i < ROWS; i++) {
            rp += W;
            float4 A2 = __ldg((const float4*)rp);
            float4 B2 = __ldg((const float4*)(rp + 4));
            float v0 = fmaf(fy, A2.x - A.x, A.x);
            float v1 = fmaf(fy, A2.y - A.y, A.y);
            float v2 = fmaf(fy, A2.z - A.z, A.z);
            float v3 = fmaf(fy, A2.w - A.w, A.w);
            float v4 = fmaf(fy, B2.x - B.x, B.x);
            float v5 = fmaf(fy, B2.y - B.y, B.y);
            float v6 = fmaf(fy, B2.z - B.z, B.z);
            float v7 = fmaf(fy, B2.w - B.w, B.w);
            float w0, w1, w2, w3, w4;
            switch (r) {
                case 0:  w0 = v0; w1 = v1; w2 = v2; w3 = v3; w4 = v4; break;
                case 1:  w0 = v1; w1 = v2; w2 = v3; w3 = v4; w4 = v5; break;
                case 2:  w0 = v2; w1 = v3; w2 = v4; w3 = v5; w4 = v6; break;
                default: w0 = v3; w1 = v4; w2 = v5; w3 = v6; w4 = v7; break;
            }
            float ox = fmaf(fx, w1 - w0, w0);
            float oy = fmaf(fx, w2 - w1, w1);
            float oz = fmaf(fx, w3 - w2, w2);
            float ow = fmaf(fx, w4 - w3, w3);
            if (SUB) {
                acc[i].x -= ox; acc[i].y -= oy; acc[i].z -= oz; acc[i].w -= ow;
            } else {
                acc[i] = make_float4(ox, oy, oz, ow);
            }
            A = A2; B = B2;
        }
    } else {
#pragma unroll 1
        for (int i = 0; i < ROWS; i++) {
            float4 o = sample_row_general(y0 + i, gx, dy, dx);
            if (SUB) {
                acc[i].x -= o.x; acc[i].y -= o.y; acc[i].z -= o.z; acc[i].w -= o.w;
            } else {
                acc[i] = o;
            }
        }
    }
}

// ---------------------------------------------------------------------------
// Main kernel: one thread -> 4x4 output tile (4 rows x 1 float4) of one pair.
// Block = 160 threads covers one full x-row span; grid = (H/ROWS, P).
// ---------------------------------------------------------------------------
__global__ void __launch_bounds__(GROUPS_PER_ROW) descriptor_kernel(
    const float* __restrict__ offs, float* __restrict__ out)
{
    int gx = threadIdx.x << 2;
    int y0 = blockIdx.x * ROWS;
    int p  = blockIdx.y;

    float4 od = __ldg((const float4*)(offs + 4 * p));  // dy1, dx1, dy2, dx2

    float4 acc[ROWS];
    do_sample<false>(y0, gx, od.x, od.y, acc);
    do_sample<true >(y0, gx, od.z, od.w, acc);

    float* op = out + ((size_t)p * H + y0) * W + gx;
#pragma unroll
    for (int i = 0; i < ROWS; i++) {
        *(float4*)(op + (size_t)i * W) = acc[i];
    }
}

extern "C" void kernel_launch(void* const* d_in, const int* in_sizes, int n_in,
                              void* d_out, int out_size) {
    const float* x    = (const float*)d_in[0];   // [1,1,480,640]
    const float* offs = (const float*)d_in[1];   // [256,2,2]
    float* out = (float*)d_out;                  // [1,256,480,640]

    const int ngroups = H * GROUPS_PER_ROW;      // 76800
    hbox_kernel<<<(ngroups + 255) / 256, 256>>>(x);
    vbox_kernel<<<(ngroups + 255) / 256, 256>>>();

    dim3 grid(H / ROWS, P, 1);                   // (120, 256)
    descriptor_kernel<<<grid, GROUPS_PER_ROW>>>(offs, out);
}

// round 8
// speedup vs baseline: 1.4204x; 1.2719x over previous
#include <cuda_runtime.h>

#define H 480
#define W 640
#define P 256
#define GROUPS_PER_ROW (W / 4)   // 160

// descriptor kernel tiling
#define TY 8                      // output rows per block
#define BAND (TY + 32)            // 40 smem rows (covers |dy|<16 band + chain)
#define GOFF 16                   // left replicate guard (floats)
#define SW (GOFF + W + 16)        // 672 floats per smem row (16B-aligned stride)
#define NTHREADS 320              // 160 cols x 2 slabs of 4 rows
#define GPAIRS 8                  // pairs per block
#define SMEM_BYTES (BAND * SW * 4)  // 107,520 B

// Scratch for box average (allocation-free per harness rules)
__device__ __align__(16) float g_tmp[H * W];
__device__ __align__(16) float g_box[H * W];

// ---------------------------------------------------------------------------
// Pass 1: horizontal 5-tap sum, edge clamp. 4 px / thread, float4 loads.
// ---------------------------------------------------------------------------
__global__ void hbox_kernel(const float* __restrict__ x) {
    int idx = blockIdx.x * blockDim.x + threadIdx.x;
    if (idx >= H * GROUPS_PER_ROW) return;
    int y = idx / GROUPS_PER_ROW;
    int t = idx - y * GROUPS_PER_ROW;
    const float* row = x + y * W;
    float4 o;
    if (t >= 1 && t <= GROUPS_PER_ROW - 2) {
        float4 m1 = *(const float4*)(row + 4 * t - 4);
        float4 c0 = *(const float4*)(row + 4 * t);
        float4 p1 = *(const float4*)(row + 4 * t + 4);
        float s = c0.x + c0.y + c0.z;
        o.x = s + m1.z + m1.w;
        o.y = s + m1.w + c0.w;
        o.z = s + c0.w + p1.x;
        o.w = c0.y + c0.z + c0.w + p1.x + p1.y;
    } else {
        float r[4];
#pragma unroll
        for (int k = 0; k < 4; k++) {
            int xx = 4 * t + k;
            float s = 0.0f;
#pragma unroll
            for (int d = -2; d <= 2; d++) {
                int xc = min(max(xx + d, 0), W - 1);
                s += row[xc];
            }
            r[k] = s;
        }
        o = make_float4(r[0], r[1], r[2], r[3]);
    }
    *(float4*)(g_tmp + y * W + 4 * t) = o;
}

// ---------------------------------------------------------------------------
// Pass 2: vertical 5-tap sum, edge clamp, /25.
// ---------------------------------------------------------------------------
__global__ void vbox_kernel() {
    int idx = blockIdx.x * blockDim.x + threadIdx.x;
    if (idx >= H * GROUPS_PER_ROW) return;
    int y = idx / GROUPS_PER_ROW;
    int t = idx - y * GROUPS_PER_ROW;
    float4 s = make_float4(0.f, 0.f, 0.f, 0.f);
#pragma unroll
    for (int d = -2; d <= 2; d++) {
        int yc = min(max(y + d, 0), H - 1);
        float4 v = *(const float4*)(g_tmp + yc * W + 4 * t);
        s.x += v.x; s.y += v.y; s.z += v.z; s.w += v.w;
    }
    const float inv = 1.0f / 25.0f;
    s.x *= inv; s.y *= inv; s.z *= inv; s.w *= inv;
    *(float4*)(g_box + y * W + 4 * t) = s;
}

// ---------------------------------------------------------------------------
// One sample from the smem band: 4 consecutive output rows, 4 cols.
// Replicate guards make this exact for all borders — no clamping needed.
// ---------------------------------------------------------------------------
template <bool SUB>
__device__ __forceinline__ void band_sample(const float* __restrict__ sb,
                                            int y0, int ybase, int gx,
                                            float dy, float dx, float4* acc) {
    float py0 = (float)ybase + dy;
    float yAf = floorf(py0);
    float fy  = py0 - yAf;
    int slot0 = (int)yAf - (y0 - 16);     // in [0, BAND-5]

    float ixf = floorf(dx);
    float fx  = dx - ixf;
    int c  = gx + (int)ixf;               // in [-16, 651]
    int bx = (c & ~3) + GOFF;             // 16B-aligned smem float index
    int rr = c & 3;                       // uniform across block

    const float* sp = sb + slot0 * SW + bx;
    float4 A = *(const float4*)sp;
    float4 B = *(const float4*)(sp + 4);
#pragma unroll
    for (int i = 0; i < 4; i++) {
        sp += SW;
        float4 A2 = *(const float4*)sp;
        float4 B2 = *(const float4*)(sp + 4);
        float v0 = fmaf(fy, A2.x - A.x, A.x);
        float v1 = fmaf(fy, A2.y - A.y, A.y);
        float v2 = fmaf(fy, A2.z - A.z, A.z);
        float v3 = fmaf(fy, A2.w - A.w, A.w);
        float v4 = fmaf(fy, B2.x - B.x, B.x);
        float v5 = fmaf(fy, B2.y - B.y, B.y);
        float v6 = fmaf(fy, B2.z - B.z, B.z);
        float v7 = fmaf(fy, B2.w - B.w, B.w);
        float w0, w1, w2, w3, w4;
        switch (rr) {
            case 0:  w0 = v0; w1 = v1; w2 = v2; w3 = v3; w4 = v4; break;
            case 1:  w0 = v1; w1 = v2; w2 = v3; w3 = v4; w4 = v5; break;
            case 2:  w0 = v2; w1 = v3; w2 = v4; w3 = v5; w4 = v6; break;
            default: w0 = v3; w1 = v4; w2 = v5; w3 = v6; w4 = v7; break;
        }
        float ox = fmaf(fx, w1 - w0, w0);
        float oy = fmaf(fx, w2 - w1, w1);
        float oz = fmaf(fx, w3 - w2, w2);
        float ow = fmaf(fx, w4 - w3, w3);
        if (SUB) {
            acc[i].x -= ox; acc[i].y -= oy; acc[i].z -= oz; acc[i].w -= ow;
        } else {
            acc[i] = make_float4(ox, oy, oz, ow);
        }
        A = A2; B = B2;
    }
}

// ---------------------------------------------------------------------------
// Descriptor kernel: block = 8-row x full-width tile; stages a 40-row
// replicate-padded band of g_box into smem, then loops over GPAIRS pairs.
// ---------------------------------------------------------------------------
__global__ void __launch_bounds__(NTHREADS) descriptor_kernel(
    const float* __restrict__ offs, float* __restrict__ out)
{
    extern __shared__ float sb[];
    const int y0  = blockIdx.x * TY;
    const int tid = threadIdx.x;

    // Stage band interior: BAND rows x 160 float4
    for (int i = tid; i < BAND * GROUPS_PER_ROW; i += NTHREADS) {
        int j = i / GROUPS_PER_ROW;
        int q = i - j * GROUPS_PER_ROW;
        int gy = min(max(y0 - 16 + j, 0), H - 1);
        float4 v = *(const float4*)(g_box + gy * W + 4 * q);
        *(float4*)(sb + j * SW + GOFF + 4 * q) = v;
    }
    // Replicate guards: 16 left + 16 right per row
    for (int i = tid; i < BAND * 32; i += NTHREADS) {
        int j = i >> 5;
        int k = i & 31;
        int gy = min(max(y0 - 16 + j, 0), H - 1);
        if (k < 16) sb[j * SW + k]            = g_box[gy * W];
        else        sb[j * SW + GOFF + W + k - 16] = g_box[gy * W + W - 1];
    }
    __syncthreads();

    const int slab  = tid / GROUPS_PER_ROW;        // 0 or 1
    const int col   = tid - slab * GROUPS_PER_ROW; // 0..159
    const int gx    = col * 4;
    const int ybase = y0 + slab * 4;

    const int pbase = blockIdx.y * GPAIRS;
#pragma unroll 1
    for (int g = 0; g < GPAIRS; g++) {
        int p = pbase + g;
        float4 od = __ldg((const float4*)(offs + 4 * p));  // dy1,dx1,dy2,dx2

        float4 acc[4];
        band_sample<false>(sb, y0, ybase, gx, od.x, od.y, acc);
        band_sample<true >(sb, y0, ybase, gx, od.z, od.w, acc);

        float* op = out + ((size_t)p * H + ybase) * W + gx;
#pragma unroll
        for (int i = 0; i < 4; i++)
            *(float4*)(op + (size_t)i * W) = acc[i];
    }
}

extern "C" void kernel_launch(void* const* d_in, const int* in_sizes, int n_in,
                              void* d_out, int out_size) {
    const float* x    = (const float*)d_in[0];   // [1,1,480,640]
    const float* offs = (const float*)d_in[1];   // [256,2,2]
    float* out = (float*)d_out;                  // [1,256,480,640]

    cudaFuncSetAttribute(descriptor_kernel,
                         cudaFuncAttributeMaxDynamicSharedMemorySize, SMEM_BYTES);

    const int ngroups = H * GROUPS_PER_ROW;      // 76800
    hbox_kernel<<<(ngroups + 255) / 256, 256>>>(x);
    vbox_kernel<<<(ngroups + 255) / 256, 256>>>();

    dim3 grid(H / TY, P / GPAIRS, 1);            // (60, 32)
    descriptor_kernel<<<grid, NTHREADS, SMEM_BYTES>>>(offs, out);
}

// round 9
// speedup vs baseline: 1.5211x; 1.0709x over previous
#include <cuda_runtime.h>
#include <cstdint>

#define H 480
#define W 640
#define P 256
#define GROUPS_PER_ROW (W / 4)   // 160

// descriptor kernel tiling
#define TY 8                      // output rows per block
#define BAND (TY + 32)            // 40 smem rows (covers |dy|<16 band + chain)
#define GOFF 16                   // left replicate guard (floats)
#define SW (GOFF + W + 16)        // 672 floats per smem row (16B-aligned stride)
#define NTHREADS 320              // 160 cols x 2 slabs of 4 rows
#define GPAIRS 8                  // pairs per block
#define SMEM_BYTES (BAND * SW * 4)  // 107,520 B

// Scratch (allocation-free per harness rules)
__device__ __align__(16) float g_box[H * W];

// ---------------------------------------------------------------------------
// Packed f32x2 helpers (Blackwell FFMA2 path — fma pipe at 2 values/op)
// ---------------------------------------------------------------------------
__device__ __forceinline__ uint64_t pk2(float lo, float hi) {
    uint64_t r; asm("mov.b64 %0, {%1, %2};" : "=l"(r) : "f"(lo), "f"(hi)); return r;
}
__device__ __forceinline__ uint64_t mul2(uint64_t a, uint64_t b) {
    uint64_t r; asm("mul.rn.f32x2 %0, %1, %2;" : "=l"(r) : "l"(a), "l"(b)); return r;
}
__device__ __forceinline__ uint64_t fma2(uint64_t a, uint64_t b, uint64_t c) {
    uint64_t r; asm("fma.rn.f32x2 %0, %1, %2, %3;" : "=l"(r) : "l"(a), "l"(b), "l"(c)); return r;
}
__device__ __forceinline__ uint64_t add2(uint64_t a, uint64_t b) {
    uint64_t r; asm("add.rn.f32x2 %0, %1, %2;" : "=l"(r) : "l"(a), "l"(b)); return r;
}
__device__ __forceinline__ float2 upk2(uint64_t a) {
    float2 f; asm("mov.b64 {%0, %1}, %2;" : "=f"(f.x), "=f"(f.y) : "l"(a)); return f;
}

// ---------------------------------------------------------------------------
// Fused 5x5 box average (separable, per-axis edge clamp). 4 px / thread.
// Recomputes the horizontal 5-tap per row (x is L1/L2 resident, flops trivial).
// ---------------------------------------------------------------------------
__global__ void box_kernel(const float* __restrict__ x) {
    int idx = blockIdx.x * blockDim.x + threadIdx.x;
    if (idx >= H * GROUPS_PER_ROW) return;
    int y = idx / GROUPS_PER_ROW;
    int t = idx - y * GROUPS_PER_ROW;

    float4 s = make_float4(0.f, 0.f, 0.f, 0.f);
    if (t >= 1 && t <= GROUPS_PER_ROW - 2) {
#pragma unroll
        for (int d = -2; d <= 2; d++) {
            int yc = min(max(y + d, 0), H - 1);
            const float* row = x + yc * W;
            float4 m1 = __ldg((const float4*)(row + 4 * t - 4));
            float4 c0 = __ldg((const float4*)(row + 4 * t));
            float4 p1 = __ldg((const float4*)(row + 4 * t + 4));
            float ss = c0.x + c0.y + c0.z;
            s.x += ss + m1.z + m1.w;
            s.y += ss + m1.w + c0.w;
            s.z += ss + c0.w + p1.x;
            s.w += c0.y + c0.z + c0.w + p1.x + p1.y;
        }
    } else {
        float r[4] = {0.f, 0.f, 0.f, 0.f};
#pragma unroll
        for (int d = -2; d <= 2; d++) {
            int yc = min(max(y + d, 0), H - 1);
            const float* row = x + yc * W;
#pragma unroll
            for (int k = 0; k < 4; k++) {
                int xx = 4 * t + k;
#pragma unroll
                for (int e = -2; e <= 2; e++) {
                    int xc = min(max(xx + e, 0), W - 1);
                    r[k] += row[xc];
                }
            }
        }
        s = make_float4(r[0], r[1], r[2], r[3]);
    }
    const float inv = 1.0f / 25.0f;
    s.x *= inv; s.y *= inv; s.z *= inv; s.w *= inv;
    *(float4*)(g_box + y * W + 4 * t) = s;
}

// ---------------------------------------------------------------------------
// Horizontal lerp of one band row: 2 LDS.128 -> 4 outputs as 2 packed pairs.
// ---------------------------------------------------------------------------
__device__ __forceinline__ void hlerp_row(const float* __restrict__ sp, int rr,
                                          uint64_t fx2, uint64_t omfx2,
                                          uint64_t& h01, uint64_t& h23) {
    float4 A  = *(const float4*)sp;
    float4 Bq = *(const float4*)(sp + 4);
    float w0, w1, w2, w3, w4;
    switch (rr) {
        case 0:  w0 = A.x; w1 = A.y; w2 = A.z; w3 = A.w; w4 = Bq.x; break;
        case 1:  w0 = A.y; w1 = A.z; w2 = A.w; w3 = Bq.x; w4 = Bq.y; break;
        case 2:  w0 = A.z; w1 = A.w; w2 = Bq.x; w3 = Bq.y; w4 = Bq.z; break;
        default: w0 = A.w; w1 = Bq.x; w2 = Bq.y; w3 = Bq.z; w4 = Bq.w; break;
    }
    uint64_t p01 = pk2(w0, w1), p12 = pk2(w1, w2);
    uint64_t p23 = pk2(w2, w3), p34 = pk2(w3, w4);
    h01 = fma2(p12, fx2, mul2(p01, omfx2));
    h23 = fma2(p34, fx2, mul2(p23, omfx2));
}

// ---------------------------------------------------------------------------
// One sample, 4 output rows x 4 cols, from the replicate-padded smem band.
// hlerp-first + vertical row chaining. SUB folds subtraction via negated fy.
// acc: 8 packed pairs (rows 0..3, pairs 01/23).
// ---------------------------------------------------------------------------
template <bool SUB>
__device__ __forceinline__ void band_sample(const float* __restrict__ sb,
                                            int y0, int ybase, int gx,
                                            float dy, float dx, uint64_t* acc) {
    float py0 = (float)ybase + dy;
    float yAf = floorf(py0);
    float fy  = py0 - yAf;
    int slot0 = (int)yAf - (y0 - 16);     // in [0, BAND-5]

    float ixf = floorf(dx);
    float fx  = dx - ixf;
    int c  = gx + (int)ixf;               // in [-16, 651]
    int bx = (c & ~3) + GOFF;             // 16B-aligned smem float index
    int rr = c & 3;                       // uniform across block

    const float sgn = SUB ? -1.0f : 1.0f;
    uint64_t fx2   = pk2(fx, fx);
    uint64_t omfx2 = pk2(1.0f - fx, 1.0f - fx);
    uint64_t fy2   = pk2(sgn * fy, sgn * fy);
    uint64_t omfy2 = pk2(sgn * (1.0f - fy), sgn * (1.0f - fy));

    const float* sp = sb + slot0 * SW + bx;
    uint64_t hp01, hp23;
    hlerp_row(sp, rr, fx2, omfx2, hp01, hp23);
#pragma unroll
    for (int i = 0; i < 4; i++) {
        sp += SW;
        uint64_t hc01, hc23;
        hlerp_row(sp, rr, fx2, omfx2, hc01, hc23);
        uint64_t o01 = fma2(hc01, fy2, mul2(hp01, omfy2));
        uint64_t o23 = fma2(hc23, fy2, mul2(hp23, omfy2));
        if (SUB) {
            acc[2 * i]     = add2(acc[2 * i], o01);
            acc[2 * i + 1] = add2(acc[2 * i + 1], o23);
        } else {
            acc[2 * i]     = o01;
            acc[2 * i + 1] = o23;
        }
        hp01 = hc01; hp23 = hc23;
    }
}

// ---------------------------------------------------------------------------
// Descriptor kernel: block = 8-row x full-width tile; stages a 40-row
// replicate-padded band of g_box into smem, then loops over GPAIRS pairs.
// ---------------------------------------------------------------------------
__global__ void __launch_bounds__(NTHREADS) descriptor_kernel(
    const float* __restrict__ offs, float* __restrict__ out)
{
    extern __shared__ float sb[];
    const int y0  = blockIdx.x * TY;
    const int tid = threadIdx.x;

    // Stage band interior: BAND rows x 160 float4
    for (int i = tid; i < BAND * GROUPS_PER_ROW; i += NTHREADS) {
        int j = i / GROUPS_PER_ROW;
        int q = i - j * GROUPS_PER_ROW;
        int gy = min(max(y0 - 16 + j, 0), H - 1);
        float4 v = *(const float4*)(g_box + gy * W + 4 * q);
        *(float4*)(sb + j * SW + GOFF + 4 * q) = v;
    }
    // Replicate guards: 16 left + 16 right per row
    for (int i = tid; i < BAND * 32; i += NTHREADS) {
        int j = i >> 5;
        int k = i & 31;
        int gy = min(max(y0 - 16 + j, 0), H - 1);
        if (k < 16) sb[j * SW + k]                 = g_box[gy * W];
        else        sb[j * SW + GOFF + W + k - 16] = g_box[gy * W + W - 1];
    }
    __syncthreads();

    const int slab  = tid / GROUPS_PER_ROW;        // 0 or 1
    const int col   = tid - slab * GROUPS_PER_ROW; // 0..159
    const int gx    = col * 4;
    const int ybase = y0 + slab * 4;

    const int pbase = blockIdx.y * GPAIRS;
#pragma unroll 1
    for (int g = 0; g < GPAIRS; g++) {
        int p = pbase + g;
        float4 od = __ldg((const float4*)(offs + 4 * p));  // dy1,dx1,dy2,dx2

        uint64_t acc[8];
        band_sample<false>(sb, y0, ybase, gx, od.x, od.y, acc);
        band_sample<true >(sb, y0, ybase, gx, od.z, od.w, acc);

        float* op = out + ((size_t)p * H + ybase) * W + gx;
#pragma unroll
        for (int i = 0; i < 4; i++) {
            float2 a = upk2(acc[2 * i]);
            float2 b = upk2(acc[2 * i + 1]);
            __stcs((float4*)(op + (size_t)i * W), make_float4(a.x, a.y, b.x, b.y));
        }
    }
}

extern "C" void kernel_launch(void* const* d_in, const int* in_sizes, int n_in,
                              void* d_out, int out_size) {
    const float* x    = (const float*)d_in[0];   // [1,1,480,640]
    const float* offs = (const float*)d_in[1];   // [256,2,2]
    float* out = (float*)d_out;                  // [1,256,480,640]

    cudaFuncSetAttribute(descriptor_kernel,
                         cudaFuncAttributeMaxDynamicSharedMemorySize, SMEM_BYTES);

    const int ngroups = H * GROUPS_PER_ROW;      // 76800
    box_kernel<<<(ngroups + 255) / 256, 256>>>(x);

    dim3 grid(H / TY, P / GPAIRS, 1);            // (60, 32)
    descriptor_kernel<<<grid, NTHREADS, SMEM_BYTES>>>(offs, out);
}

// round 10
// speedup vs baseline: 1.7552x; 1.1539x over previous
#include <cuda_runtime.h>
#include <cstdint>

#define H 480
#define W 640
#define P 256
#define GROUPS_PER_ROW (W / 4)   // 160

// descriptor kernel tiling
#define TY 8                      // output rows per block (one 8-row chain)
#define BAND (TY + 32)            // 40 smem rows (covers |dy|<=16 band)
#define GOFF 16                   // left replicate guard (floats)
#define SW (GOFF + W + 16)        // 672 floats per smem row
#define NTHREADS 160              // one thread per float4 column
#define GPAIRS 16                 // pairs per block
#define SMEM_BYTES (BAND * SW * 4)  // 107,520 B

// Scratch (allocation-free per harness rules)
__device__ __align__(16) float g_box[H * W];

// ---------------------------------------------------------------------------
// Packed f32x2 helpers (Blackwell FFMA2 path)
// ---------------------------------------------------------------------------
__device__ __forceinline__ uint64_t pk2(float lo, float hi) {
    uint64_t r; asm("mov.b64 %0, {%1, %2};" : "=l"(r) : "f"(lo), "f"(hi)); return r;
}
__device__ __forceinline__ uint64_t mul2(uint64_t a, uint64_t b) {
    uint64_t r; asm("mul.rn.f32x2 %0, %1, %2;" : "=l"(r) : "l"(a), "l"(b)); return r;
}
__device__ __forceinline__ uint64_t fma2(uint64_t a, uint64_t b, uint64_t c) {
    uint64_t r; asm("fma.rn.f32x2 %0, %1, %2, %3;" : "=l"(r) : "l"(a), "l"(b), "l"(c)); return r;
}
__device__ __forceinline__ uint64_t add2(uint64_t a, uint64_t b) {
    uint64_t r; asm("add.rn.f32x2 %0, %1, %2;" : "=l"(r) : "l"(a), "l"(b)); return r;
}
__device__ __forceinline__ float2 upk2(uint64_t a) {
    float2 f; asm("mov.b64 {%0, %1}, %2;" : "=f"(f.x), "=f"(f.y) : "l"(a)); return f;
}

// ---------------------------------------------------------------------------
// Fused 5x5 box average (separable, per-axis edge clamp). 4 px / thread.
// ---------------------------------------------------------------------------
__global__ void box_kernel(const float* __restrict__ x) {
    int idx = blockIdx.x * blockDim.x + threadIdx.x;
    if (idx >= H * GROUPS_PER_ROW) return;
    int y = idx / GROUPS_PER_ROW;
    int t = idx - y * GROUPS_PER_ROW;

    float4 s = make_float4(0.f, 0.f, 0.f, 0.f);
    if (t >= 1 && t <= GROUPS_PER_ROW - 2) {
#pragma unroll
        for (int d = -2; d <= 2; d++) {
            int yc = min(max(y + d, 0), H - 1);
            const float* row = x + yc * W;
            float4 m1 = __ldg((const float4*)(row + 4 * t - 4));
            float4 c0 = __ldg((const float4*)(row + 4 * t));
            float4 p1 = __ldg((const float4*)(row + 4 * t + 4));
            float ss = c0.x + c0.y + c0.z;
            s.x += ss + m1.z + m1.w;
            s.y += ss + m1.w + c0.w;
            s.z += ss + c0.w + p1.x;
            s.w += c0.y + c0.z + c0.w + p1.x + p1.y;
        }
    } else {
        float r[4] = {0.f, 0.f, 0.f, 0.f};
#pragma unroll
        for (int d = -2; d <= 2; d++) {
            int yc = min(max(y + d, 0), H - 1);
            const float* row = x + yc * W;
#pragma unroll
            for (int k = 0; k < 4; k++) {
                int xx = 4 * t + k;
#pragma unroll
                for (int e = -2; e <= 2; e++) {
                    int xc = min(max(xx + e, 0), W - 1);
                    r[k] += row[xc];
                }
            }
        }
        s = make_float4(r[0], r[1], r[2], r[3]);
    }
    const float inv = 1.0f / 25.0f;
    s.x *= inv; s.y *= inv; s.z *= inv; s.w *= inv;
    *(float4*)(g_box + y * W + 4 * t) = s;
}

// ---------------------------------------------------------------------------
// Horizontal lerp of one band row, compile-time window shift RR.
// 2 LDS.128 -> 4 outputs as 2 packed pairs.
// ---------------------------------------------------------------------------
template <int RR>
__device__ __forceinline__ void hrow(const float* __restrict__ sp,
                                     uint64_t fx2, uint64_t omfx2,
                                     uint64_t& h0, uint64_t& h1) {
    float4 A = *(const float4*)sp;
    float4 B = *(const float4*)(sp + 4);
    float w0, w1, w2, w3, w4;
    if      (RR == 0) { w0 = A.x; w1 = A.y; w2 = A.z; w3 = A.w; w4 = B.x; }
    else if (RR == 1) { w0 = A.y; w1 = A.z; w2 = A.w; w3 = B.x; w4 = B.y; }
    else if (RR == 2) { w0 = A.z; w1 = A.w; w2 = B.x; w3 = B.y; w4 = B.z; }
    else              { w0 = A.w; w1 = B.x; w2 = B.y; w3 = B.z; w4 = B.w; }
    h0 = fma2(pk2(w1, w2), fx2, mul2(pk2(w0, w1), omfx2));
    h1 = fma2(pk2(w3, w4), fx2, mul2(pk2(w2, w3), omfx2));
}

// ---------------------------------------------------------------------------
// 8-row chained sample: 9 band-row hlerps -> 8 vlerped output rows.
// SUB folds the pair subtraction via negated fy weights.
// acc: 16 packed pairs (rows 0..7, pairs 01/23).
// ---------------------------------------------------------------------------
template <int RR, bool SUB>
__device__ __forceinline__ void rows8(const float* __restrict__ sp,
                                      float fx, float fy, uint64_t* acc) {
    uint64_t fx2   = pk2(fx, fx);
    uint64_t omfx2 = pk2(1.0f - fx, 1.0f - fx);
    const float sgn = SUB ? -1.0f : 1.0f;
    uint64_t fy2   = pk2(sgn * fy, sgn * fy);
    uint64_t omfy2 = pk2(sgn * (1.0f - fy), sgn * (1.0f - fy));

    uint64_t hp0, hp1;
    hrow<RR>(sp, fx2, omfx2, hp0, hp1);
#pragma unroll
    for (int i = 0; i < TY; i++) {
        sp += SW;
        uint64_t hc0, hc1;
        hrow<RR>(sp, fx2, omfx2, hc0, hc1);
        uint64_t o0 = fma2(hc0, fy2, mul2(hp0, omfy2));
        uint64_t o1 = fma2(hc1, fy2, mul2(hp1, omfy2));
        if (SUB) {
            acc[2 * i]     = add2(acc[2 * i], o0);
            acc[2 * i + 1] = add2(acc[2 * i + 1], o1);
        } else {
            acc[2 * i]     = o0;
            acc[2 * i + 1] = o1;
        }
        hp0 = hc0; hp1 = hc1;
    }
}

template <bool SUB>
__device__ __forceinline__ void band_sample8(const float* __restrict__ sb,
                                             int y0, int gx,
                                             float dy, float dx, uint64_t* acc) {
    float py0 = (float)y0 + dy;
    float yAf = floorf(py0);
    float fy  = py0 - yAf;
    int slot0 = (int)yAf - (y0 - 16);      // in [0, 31]

    float ixf = floorf(dx);
    float fx  = dx - ixf;
    int c  = gx + (int)ixf;                // in [-16, 651]
    int bx = (c & ~3) + GOFF;
    int rr = c & 3;                        // block-uniform

    const float* sp = sb + slot0 * SW + bx;
    switch (rr) {                          // uniform branch -> no divergence
        case 0:  rows8<0, SUB>(sp, fx, fy, acc); break;
        case 1:  rows8<1, SUB>(sp, fx, fy, acc); break;
        case 2:  rows8<2, SUB>(sp, fx, fy, acc); break;
        default: rows8<3, SUB>(sp, fx, fy, acc); break;
    }
}

// ---------------------------------------------------------------------------
// Descriptor kernel: stages a 40-row replicate-padded band of g_box into
// smem once, then loops over 16 pairs. One thread = 8 rows x 4 cols.
// ---------------------------------------------------------------------------
__global__ void __launch_bounds__(NTHREADS) descriptor_kernel(
    const float* __restrict__ offs, float* __restrict__ out)
{
    extern __shared__ float sb[];
    const int y0  = blockIdx.x * TY;
    const int tid = threadIdx.x;           // 0..159 -> one float4 column

    // Stage band interior: one float4 per thread per row
#pragma unroll 4
    for (int j = 0; j < BAND; j++) {
        int gy = min(max(y0 - 16 + j, 0), H - 1);
        *(float4*)(sb + j * SW + GOFF + 4 * tid) =
            *(const float4*)(g_box + gy * W + 4 * tid);
    }
    // Replicate guards: 16 left + 16 right per row
    for (int i = tid; i < BAND * 32; i += NTHREADS) {
        int j = i >> 5;
        int k = i & 31;
        int gy = min(max(y0 - 16 + j, 0), H - 1);
        if (k < 16) sb[j * SW + k]                 = g_box[gy * W];
        else        sb[j * SW + GOFF + W + k - 16] = g_box[gy * W + W - 1];
    }
    __syncthreads();

    const int gx = tid * 4;
    const int pbase = blockIdx.y * GPAIRS;
#pragma unroll 1
    for (int g = 0; g < GPAIRS; g++) {
        int p = pbase + g;
        float4 od = __ldg((const float4*)(offs + 4 * p));  // dy1,dx1,dy2,dx2

        uint64_t acc[2 * TY];
        band_sample8<false>(sb, y0, gx, od.x, od.y, acc);
        band_sample8<true >(sb, y0, gx, od.z, od.w, acc);

        float* op = out + ((size_t)p * H + y0) * W + gx;
#pragma unroll
        for (int i = 0; i < TY; i++) {
            float2 a = upk2(acc[2 * i]);
            float2 b = upk2(acc[2 * i + 1]);
            __stcs((float4*)(op + (size_t)i * W), make_float4(a.x, a.y, b.x, b.y));
        }
    }
}

extern "C" void kernel_launch(void* const* d_in, const int* in_sizes, int n_in,
                              void* d_out, int out_size) {
    const float* x    = (const float*)d_in[0];   // [1,1,480,640]
    const float* offs = (const float*)d_in[1];   // [256,2,2]
    float* out = (float*)d_out;                  // [1,256,480,640]

    cudaFuncSetAttribute(descriptor_kernel,
                         cudaFuncAttributeMaxDynamicSharedMemorySize, SMEM_BYTES);

    const int ngroups = H * GROUPS_PER_ROW;      // 76800
    box_kernel<<<(ngroups + 255) / 256, 256>>>(x);

    dim3 grid(H / TY, P / GPAIRS, 1);            // (60, 16)
    descriptor_kernel<<<grid, NTHREADS, SMEM_BYTES>>>(offs, out);
}

// round 11
// speedup vs baseline: 1.8879x; 1.0756x over previous
#include <cuda_runtime.h>
#include <cstdint>

#define H 480
#define W 640
#define P 256

// swizzled, guard-padded row layout (shared by g_box and the smem band)
#define SWQ 176                   // 16B quads per row (multiple of 16!)
#define SWF (SWQ * 4)             // 704 floats per row
#define GQ  4                     // left guard quads (16 floats)

// descriptor tiling
#define TY 16                     // output rows per block
#define BAND (TY + 32)            // 48 band rows
#define NTHREADS 320              // 80 col-threads x 4 row slabs
#define GPAIRS 8
#define SMEM_DATA_BYTES (BAND * SWF * 4)        // 135168
#define SMEM_BYTES (SMEM_DATA_BYTES + 16)       // + mbarrier

// Pre-swizzled box-average image with replicate guards (allocation-free)
__device__ __align__(16) float g_box[H * SWF];

// 16B-quad XOR swizzle: makes stride-2-quad (32B lane stride) LDS conflict-free
__device__ __host__ __forceinline__ int swzq(int q) { return q ^ ((q >> 3) & 1); }

// ---------------------------------------------------------------------------
// Packed f32x2 helpers
// ---------------------------------------------------------------------------
__device__ __forceinline__ uint64_t pk2(float lo, float hi) {
    uint64_t r; asm("mov.b64 %0, {%1, %2};" : "=l"(r) : "f"(lo), "f"(hi)); return r;
}
__device__ __forceinline__ uint64_t mul2(uint64_t a, uint64_t b) {
    uint64_t r; asm("mul.rn.f32x2 %0, %1, %2;" : "=l"(r) : "l"(a), "l"(b)); return r;
}
__device__ __forceinline__ uint64_t fma2(uint64_t a, uint64_t b, uint64_t c) {
    uint64_t r; asm("fma.rn.f32x2 %0, %1, %2, %3;" : "=l"(r) : "l"(a), "l"(b), "l"(c)); return r;
}
__device__ __forceinline__ uint64_t add2(uint64_t a, uint64_t b) {
    uint64_t r; asm("add.rn.f32x2 %0, %1, %2;" : "=l"(r) : "l"(a), "l"(b)); return r;
}
__device__ __forceinline__ float2 upk2(uint64_t a) {
    float2 f; asm("mov.b64 {%0, %1}, %2;" : "=f"(f.x), "=f"(f.y) : "l"(a)); return f;
}

// ---------------------------------------------------------------------------
// Fused 5x5 box average -> pre-swizzled guard-padded g_box.
// 168 groups per row: 160 interior float4 + 4 left-guard + 4 right-guard quads.
// ---------------------------------------------------------------------------
__global__ void box_kernel(const float* __restrict__ x) {
    int idx = blockIdx.x * blockDim.x + threadIdx.x;
    if (idx >= H * 168) return;
    int y = idx / 168;
    int t = idx - y * 168;
    float* orow = g_box + y * SWF;

    if (t < 160) {
        float4 s = make_float4(0.f, 0.f, 0.f, 0.f);
        if (t >= 1 && t <= 158) {
#pragma unroll
            for (int d = -2; d <= 2; d++) {
                int yc = min(max(y + d, 0), H - 1);
                const float* row = x + yc * W;
                float4 m1 = __ldg((const float4*)(row + 4 * t - 4));
                float4 c0 = __ldg((const float4*)(row + 4 * t));
                float4 p1 = __ldg((const float4*)(row + 4 * t + 4));
                float ss = c0.x + c0.y + c0.z;
                s.x += ss + m1.z + m1.w;
                s.y += ss + m1.w + c0.w;
                s.z += ss + c0.w + p1.x;
                s.w += c0.y + c0.z + c0.w + p1.x + p1.y;
            }
        } else {
            float r[4] = {0.f, 0.f, 0.f, 0.f};
#pragma unroll
            for (int d = -2; d <= 2; d++) {
                int yc = min(max(y + d, 0), H - 1);
                const float* row = x + yc * W;
#pragma unroll
                for (int k = 0; k < 4; k++) {
                    int xx = 4 * t + k;
#pragma unroll
                    for (int e = -2; e <= 2; e++) {
                        int xc = min(max(xx + e, 0), W - 1);
                        r[k] += row[xc];
                    }
                }
            }
            s = make_float4(r[0], r[1], r[2], r[3]);
        }
        const float inv = 1.0f / 25.0f;
        s.x *= inv; s.y *= inv; s.z *= inv; s.w *= inv;
        *(float4*)(orow + swzq(GQ + t) * 4) = s;
    } else {
        // guard quads: replicate border box value
        bool left = (t < 164);
        float v = 0.f;
#pragma unroll
        for (int d = -2; d <= 2; d++) {
            int yc = min(max(y + d, 0), H - 1);
            const float* row = x + yc * W;
            if (left) v += 3.f * row[0] + row[1] + row[2];
            else      v += 3.f * row[W - 1] + row[W - 2] + row[W - 3];
        }
        v *= (1.0f / 25.0f);
        int q = left ? (t - 160) : (GQ + 160 + (t - 164));  // 0..3 or 164..167
        *(float4*)(orow + swzq(q) * 4) = make_float4(v, v, v, v);
    }
}

// ---------------------------------------------------------------------------
// Horizontal lerp of one band row: 3 swizzled LDS.128 -> 8 outputs (4 pairs)
// ---------------------------------------------------------------------------
template <int RR>
__device__ __forceinline__ void hrow8(const float* __restrict__ sp,
                                      int o0, int o1, int o2,
                                      uint64_t fx2, uint64_t omfx2, uint64_t* h) {
    float4 A = *(const float4*)(sp + o0);
    float4 B = *(const float4*)(sp + o1);
    float4 C = *(const float4*)(sp + o2);
    float w0, w1, w2, w3, w4, w5, w6, w7, w8;
    if      (RR == 0) { w0=A.x; w1=A.y; w2=A.z; w3=A.w; w4=B.x; w5=B.y; w6=B.z; w7=B.w; w8=C.x; }
    else if (RR == 1) { w0=A.y; w1=A.z; w2=A.w; w3=B.x; w4=B.y; w5=B.z; w6=B.w; w7=C.x; w8=C.y; }
    else if (RR == 2) { w0=A.z; w1=A.w; w2=B.x; w3=B.y; w4=B.z; w5=B.w; w6=C.x; w7=C.y; w8=C.z; }
    else              { w0=A.w; w1=B.x; w2=B.y; w3=B.z; w4=B.w; w5=C.x; w6=C.y; w7=C.z; w8=C.w; }
    h[0] = fma2(pk2(w1, w2), fx2, mul2(pk2(w0, w1), omfx2));
    h[1] = fma2(pk2(w3, w4), fx2, mul2(pk2(w2, w3), omfx2));
    h[2] = fma2(pk2(w5, w6), fx2, mul2(pk2(w4, w5), omfx2));
    h[3] = fma2(pk2(w7, w8), fx2, mul2(pk2(w6, w7), omfx2));
}

// ---------------------------------------------------------------------------
// 4-row chained sample, 8 cols wide. SUB folds subtraction via negated fy.
// acc: 16 packed pairs (4 rows x 4 pairs).
// ---------------------------------------------------------------------------
template <int RR, bool SUB>
__device__ __forceinline__ void rows4x8(const float* __restrict__ sp,
                                        int o0, int o1, int o2,
                                        float fx, float fy, uint64_t* acc) {
    uint64_t fx2   = pk2(fx, fx);
    uint64_t omfx2 = pk2(1.0f - fx, 1.0f - fx);
    const float sgn = SUB ? -1.0f : 1.0f;
    uint64_t fy2   = pk2(sgn * fy, sgn * fy);
    uint64_t omfy2 = pk2(sgn * (1.0f - fy), sgn * (1.0f - fy));

    uint64_t hp[4], hc[4];
    hrow8<RR>(sp, o0, o1, o2, fx2, omfx2, hp);
#pragma unroll
    for (int i = 0; i < 4; i++) {
        sp += SWF;
        hrow8<RR>(sp, o0, o1, o2, fx2, omfx2, hc);
#pragma unroll
        for (int k = 0; k < 4; k++) {
            uint64_t o = fma2(hc[k], fy2, mul2(hp[k], omfy2));
            if (SUB) acc[4 * i + k] = add2(acc[4 * i + k], o);
            else     acc[4 * i + k] = o;
            hp[k] = hc[k];
        }
    }
}

template <bool SUB>
__device__ __forceinline__ void band_sample(const float* __restrict__ sb,
                                            int y0, int ybase, int gx,
                                            float dy, float dx, uint64_t* acc) {
    float py0 = (float)ybase + dy;
    float yAf = floorf(py0);
    float fy  = py0 - yAf;
    int slot0 = (int)yAf - (y0 - 16);     // in [0, BAND-5]

    float ixf = floorf(dx);
    float fx  = dx - ixf;
    int c  = gx + (int)ixf;               // in [-16, 647]
    int qb = (c >> 2) + GQ;               // quad index incl guard, [0, 165]
    int rr = c & 3;                       // block-uniform
    int o0 = swzq(qb) * 4, o1 = swzq(qb + 1) * 4, o2 = swzq(qb + 2) * 4;

    const float* sp = sb + slot0 * SWF;
    switch (rr) {                         // uniform branch
        case 0:  rows4x8<0, SUB>(sp, o0, o1, o2, fx, fy, acc); break;
        case 1:  rows4x8<1, SUB>(sp, o0, o1, o2, fx, fy, acc); break;
        case 2:  rows4x8<2, SUB>(sp, o0, o1, o2, fx, fy, acc); break;
        default: rows4x8<3, SUB>(sp, o0, o1, o2, fx, fy, acc); break;
    }
}

// ---------------------------------------------------------------------------
// Descriptor kernel: TMA-bulk stages a 48-row pre-swizzled band (guards
// included in the linear copy), then 80 cols x 4 slabs compute 8 pairs.
// ---------------------------------------------------------------------------
__global__ void __launch_bounds__(NTHREADS) descriptor_kernel(
    const float* __restrict__ offs, float* __restrict__ out)
{
    extern __shared__ float sb[];
    const int y0  = blockIdx.x * TY;
    const int tid = threadIdx.x;
    uint32_t sbu  = (uint32_t)__cvta_generic_to_shared(sb);
    uint32_t mbar = sbu + SMEM_DATA_BYTES;

    if (tid == 0) {
        asm volatile("mbarrier.init.shared.b64 [%0], 1;" :: "r"(mbar) : "memory");
        asm volatile("mbarrier.arrive.expect_tx.shared.b64 _, [%0], %1;"
                     :: "r"(mbar), "r"((uint32_t)(BAND * SWF * 4)) : "memory");
    }
    __syncthreads();
    if (tid < BAND) {
        int gy = min(max(y0 - 16 + tid, 0), H - 1);
        uint32_t dst = sbu + tid * (SWF * 4);
        const float* src = g_box + gy * SWF;
        asm volatile(
            "cp.async.bulk.shared::cluster.global.mbarrier::complete_tx::bytes "
            "[%0], [%1], %2, [%3];"
            :: "r"(dst), "l"(src), "r"((uint32_t)(SWF * 4)), "r"(mbar) : "memory");
    }
    // all threads wait for band (parity 0, acquire)
    {
        uint32_t done;
        asm volatile(
            "{\n\t.reg .pred p;\n\t"
            "mbarrier.try_wait.parity.acquire.cta.shared::cta.b64 p, [%1], %2;\n\t"
            "selp.b32 %0, 1, 0, p;\n\t}"
            : "=r"(done) : "r"(mbar), "r"(0u) : "memory");
        if (!done) {
            asm volatile(
                "{\n\t.reg .pred P1;\n\t"
                "WL%=:\n\t"
                "mbarrier.try_wait.parity.acquire.cta.shared::cta.b64 P1, [%0], %1, 0x989680;\n\t"
                "@P1 bra.uni WD%=;\n\t"
                "bra.uni WL%=;\n\t"
                "WD%=:\n\t}"
                :: "r"(mbar), "r"(0u) : "memory");
        }
    }

    const int slab  = tid / 80;            // 0..3 (phase-aligned boundaries)
    const int col   = tid - slab * 80;     // 0..79
    const int gx    = col * 8;
    const int ybase = y0 + slab * 4;

    const int pbase = blockIdx.y * GPAIRS;
#pragma unroll 1
    for (int g = 0; g < GPAIRS; g++) {
        int p = pbase + g;
        float4 od = __ldg((const float4*)(offs + 4 * p));  // dy1,dx1,dy2,dx2

        uint64_t acc[16];
        band_sample<false>(sb, y0, ybase, gx, od.x, od.y, acc);
        band_sample<true >(sb, y0, ybase, gx, od.z, od.w, acc);

        float* op = out + ((size_t)p * H + ybase) * W + gx;
#pragma unroll
        for (int i = 0; i < 4; i++) {
            float2 a = upk2(acc[4 * i + 0]);
            float2 b = upk2(acc[4 * i + 1]);
            float2 c = upk2(acc[4 * i + 2]);
            float2 d = upk2(acc[4 * i + 3]);
            __stcs((float4*)(op + (size_t)i * W),     make_float4(a.x, a.y, b.x, b.y));
            __stcs((float4*)(op + (size_t)i * W + 4), make_float4(c.x, c.y, d.x, d.y));
        }
    }
}

extern "C" void kernel_launch(void* const* d_in, const int* in_sizes, int n_in,
                              void* d_out, int out_size) {
    const float* x    = (const float*)d_in[0];   // [1,1,480,640]
    const float* offs = (const float*)d_in[1];   // [256,2,2]
    float* out = (float*)d_out;                  // [1,256,480,640]

    cudaFuncSetAttribute(descriptor_kernel,
                         cudaFuncAttributeMaxDynamicSharedMemorySize, SMEM_BYTES);

    const int nbox = H * 168;                    // 80640
    box_kernel<<<(nbox + 255) / 256, 256>>>(x);

    dim3 grid(H / TY, P / GPAIRS, 1);            // (30, 32) = 960 blocks
    descriptor_kernel<<<grid, NTHREADS, SMEM_BYTES>>>(offs, out);
}